// round 12
// baseline (speedup 1.0000x reference)
#include <cuda_runtime.h>

// ============================================================================
// Convert2ImageLayer: out[b,h,w,:] = feat[b, slic[b,h,w]-1, :]  (0 if invalid)
// Shapes: B=8, N=1024, C=128, H=W=512.
//
// Configuration = measured optimum (R2, reproduced 6x at 141.8-143.7 us):
//   one warp per P=4 pixels, lane l owns float4-chunk l, MLP=4 independent
//   LDG.128 gathers, coalesced 512B store bursts, 65536 x 256-thr CTAs.
//
// R12 one-variable probe: store cache-op __stcs (evict-first, write-back)
// -> __stwt (write-through). Output is write-once/never-read; write-through
// removes dirty-line bookkeeping in L2 and issues DRAM writes earlier.
// Expected neutral (LTS cap is path-independent); any upside is from the
// L2 write-back/eviction turnaround in the residual 6% vs spec.
// ============================================================================

static constexpr int  Nc = 1024;
static constexpr int  C4 = 32;            // 128 floats = 32 float4 per pixel
static constexpr int  HW_SHIFT = 18;      // H*W = 2^18 pixels per batch image
static constexpr long long PIX = 8LL << HW_SHIFT;   // 2,097,152 pixels
static constexpr int  P = 4;              // pixels per warp (measured optimum)

__global__ void __launch_bounds__(256)
convert2image_gather4wt(const float4* __restrict__ feat,   // [B, N, C/4]
                        const int*    __restrict__ slic,   // [B*H*W]
                        float4*       __restrict__ out)    // [B*H*W, C/4]
{
    const long long warp_gid = (long long)blockIdx.x * (blockDim.x >> 5)
                             + (threadIdx.x >> 5);
    const long long pix0 = warp_gid * P;
    const int lane = threadIdx.x & 31;

    if (pix0 >= PIX) return;

    // All P pixels of a warp lie in the same batch image (P divides H*W).
    const int b = (int)(pix0 >> HW_SHIFT);
    const float4* __restrict__ fb = feat + ((long long)b * Nc) * C4;

    // Lanes 0..P-1 fetch the P segment labels (one 16B sector total).
    int myidx = 0;
    if (lane < P) myidx = __ldg(slic + pix0 + lane) - 1;   // labels 1-indexed

    float4 v[P];
    #pragma unroll
    for (int p = 0; p < P; p++) {
        const int idx = __shfl_sync(0xffffffffu, myidx, p);
        v[p] = make_float4(0.f, 0.f, 0.f, 0.f);
        if ((unsigned)idx < (unsigned)Nc) {
            v[p] = __ldg(fb + (long long)idx * C4 + lane);  // independent -> MLP=P
        }
    }

    float4* __restrict__ o = out + (pix0 << 5) + lane;
    #pragma unroll
    for (int p = 0; p < P; p++) {
        __stwt(o + (p << 5), v[p]);    // write-through: write-once, never read
    }
}

extern "C" void kernel_launch(void* const* d_in, const int* in_sizes, int n_in,
                              void* d_out, int out_size)
{
    const float4* feat = (const float4*)d_in[0];   // graph_lstm_output fp32 [B,N,C]
    const int*    slic = (const int*)d_in[1];      // slic_output int32 [B,H,W,1]
    float4*       out  = (float4*)d_out;           // fp32 [B,H,W,C]

    const int threads = 256;                        // 8 warps -> 32 pixels/block
    const long long pixels_per_block = (threads / 32) * P;
    const unsigned blocks = (unsigned)((PIX + pixels_per_block - 1) / pixels_per_block); // 65,536

    convert2image_gather4wt<<<blocks, threads>>>(feat, slic, out);
}

// round 13
// speedup vs baseline: 1.0781x; 1.0781x over previous
#include <cuda_runtime.h>

// ============================================================================
// Convert2ImageLayer: out[b,h,w,:] = feat[b, slic[b,h,w]-1, :]  (0 if invalid)
// Shapes: B=8, N=1024, C=128, H=W=512.
//
// FINAL kernel — HBM-write-roofline reached.
//   compulsory traffic: 1.074 GB output writes (+12 MB reads) -> 134 us floor
//   measured: 141.8 us best (reproduced 6x in 141.8-143.7 band)
//           = 7.6 TB/s effective = 95% of 8 TB/s spec
//
// Full knob sweep (12 rounds, all post-mortemed):
//   - per-thread MLP 1/2/4/8: MLP=4 independent LDG.128 gathers is the entire
//     win (260us -> 142us); beyond 4 ptxas reuse / occupancy eats it.
//   - granularity: 65536 small CTAs (8 warps, 4 pix/warp) optimal; every
//     coarser variant (P=8, 512-thr, S=4 software pipeline) 1-4us worse.
//   - 256-bit LDG/STG (sm_100 v8.f32): worse both times (loses MLP or regs).
//   - store cache-op: __stcs (write-back, evict-first) beats __stwt by 11us —
//     write-back coalesces full 128B lines before DRAM drain; evict-first
//     keeps the 4MB feature table L2-resident for the gather reads.
//   - residual ~6% vs spec = DRAM refresh + R/W turnaround; unreachable.
// ============================================================================

static constexpr int  Nc = 1024;
static constexpr int  C4 = 32;            // 128 floats = 32 float4 per pixel
static constexpr int  HW_SHIFT = 18;      // H*W = 2^18 pixels per batch image
static constexpr long long PIX = 8LL << HW_SHIFT;   // 2,097,152 pixels
static constexpr int  P = 4;              // pixels per warp (measured optimum)

__global__ void __launch_bounds__(256)
convert2image_gather4(const float4* __restrict__ feat,   // [B, N, C/4]
                      const int*    __restrict__ slic,   // [B*H*W]
                      float4*       __restrict__ out)    // [B*H*W, C/4]
{
    const long long warp_gid = (long long)blockIdx.x * (blockDim.x >> 5)
                             + (threadIdx.x >> 5);
    const long long pix0 = warp_gid * P;
    const int lane = threadIdx.x & 31;

    if (pix0 >= PIX) return;

    // All P pixels of a warp lie in the same batch image (P divides H*W).
    const int b = (int)(pix0 >> HW_SHIFT);
    const float4* __restrict__ fb = feat + ((long long)b * Nc) * C4;

    // Lanes 0..P-1 fetch the P segment labels (one 16B sector total).
    int myidx = 0;
    if (lane < P) myidx = __ldg(slic + pix0 + lane) - 1;   // labels 1-indexed

    float4 v[P];
    #pragma unroll
    for (int p = 0; p < P; p++) {
        const int idx = __shfl_sync(0xffffffffu, myidx, p);
        v[p] = make_float4(0.f, 0.f, 0.f, 0.f);
        if ((unsigned)idx < (unsigned)Nc) {
            v[p] = __ldg(fb + (long long)idx * C4 + lane);  // independent -> MLP=P
        }
    }

    float4* __restrict__ o = out + (pix0 << 5) + lane;
    #pragma unroll
    for (int p = 0; p < P; p++) {
        __stcs(o + (p << 5), v[p]);    // streaming: write-once, evict-first
    }
}

extern "C" void kernel_launch(void* const* d_in, const int* in_sizes, int n_in,
                              void* d_out, int out_size)
{
    const float4* feat = (const float4*)d_in[0];   // graph_lstm_output fp32 [B,N,C]
    const int*    slic = (const int*)d_in[1];      // slic_output int32 [B,H,W,1]
    float4*       out  = (float4*)d_out;           // fp32 [B,H,W,C]

    const int threads = 256;                        // 8 warps -> 32 pixels/block
    const long long pixels_per_block = (threads / 32) * P;
    const unsigned blocks = (unsigned)((PIX + pixels_per_block - 1) / pixels_per_block); // 65,536

    convert2image_gather4<<<blocks, threads>>>(feat, slic, out);
}

// round 14
// speedup vs baseline: 1.0818x; 1.0034x over previous
#include <cuda_runtime.h>

// ============================================================================
// Convert2ImageLayer: out[b,h,w,:] = feat[b, slic[b,h,w]-1, :]  (0 if invalid)
// Shapes: B=8, N=1024, C=128, H=W=512.
//
// FINAL kernel — HBM-write-roofline.
//   compulsory traffic: 1.074 GB writes (+12 MB reads) -> 134 us floor
//   measured plateau: 141.8-143.7 us over 7 reproductions = ~7.6 TB/s = 95% spec
//
// Configuration (full 13-round sweep, all post-mortemed):
//   - one warp per P=4 pixels, lane l owns float4-chunk l of the 512B row
//   - MLP=4 independent LDG.128 gathers per thread (the entire win, 260->142us;
//     MLP 2/8 and 256-bit v8 ops all measured worse)
//   - 65536 x 256-thr CTAs (coarser granularity variants 1-4us worse)
//   - __stcs write-back streaming stores (beats __stwt by 11us: write-back
//     coalesces full 128B lines; evict-first keeps 4MB feat table L2-resident)
// R14 micro-cleanups (zero-risk): single LDG.128 int4 index load on lane 0
// (replaces predicated per-lane load), bounds guard removed (grid exact).
// ============================================================================

static constexpr int  Nc = 1024;
static constexpr int  C4 = 32;            // 128 floats = 32 float4 per pixel
static constexpr int  HW_SHIFT = 18;      // H*W = 2^18 pixels per batch image
static constexpr int  P = 4;              // pixels per warp (measured optimum)

__global__ void __launch_bounds__(256)
convert2image_gather4(const float4* __restrict__ feat,   // [B, N, C/4]
                      const int4*   __restrict__ slic4,  // [B*H*W/4] packed labels
                      float4*       __restrict__ out)    // [B*H*W, C/4]
{
    const long long warp_gid = (long long)blockIdx.x * (blockDim.x >> 5)
                             + (threadIdx.x >> 5);
    const long long pix0 = warp_gid * P;      // grid covers PIX exactly; no guard
    const int lane = threadIdx.x & 31;

    // All P pixels of a warp lie in the same batch image (P divides H*W).
    const int b = (int)(pix0 >> HW_SHIFT);
    const float4* __restrict__ fb = feat + ((long long)b * Nc) * C4;

    // Lane 0 loads all four labels with one LDG.128 (16B sector); shfl parts.
    int4 li = make_int4(0, 0, 0, 0);
    if (lane == 0) li = __ldg(slic4 + warp_gid);

    const int i0 = __shfl_sync(0xffffffffu, li.x, 0) - 1;   // labels 1-indexed
    const int i1 = __shfl_sync(0xffffffffu, li.y, 0) - 1;
    const int i2 = __shfl_sync(0xffffffffu, li.z, 0) - 1;
    const int i3 = __shfl_sync(0xffffffffu, li.w, 0) - 1;
    const int idx[P] = { i0, i1, i2, i3 };

    float4 v[P];
    #pragma unroll
    for (int p = 0; p < P; p++) {
        v[p] = make_float4(0.f, 0.f, 0.f, 0.f);
        if ((unsigned)idx[p] < (unsigned)Nc) {
            v[p] = __ldg(fb + (long long)idx[p] * C4 + lane);  // independent -> MLP=P
        }
    }

    float4* __restrict__ o = out + (pix0 << 5) + lane;
    #pragma unroll
    for (int p = 0; p < P; p++) {
        __stcs(o + (p << 5), v[p]);    // streaming: write-once, evict-first
    }
}

extern "C" void kernel_launch(void* const* d_in, const int* in_sizes, int n_in,
                              void* d_out, int out_size)
{
    const float4* feat  = (const float4*)d_in[0];  // graph_lstm_output fp32 [B,N,C]
    const int4*   slic4 = (const int4*)d_in[1];    // slic_output int32 [B,H,W,1], 16B-aligned
    float4*       out   = (float4*)d_out;          // fp32 [B,H,W,C]

    const int threads = 256;                        // 8 warps -> 32 pixels/block
    const unsigned blocks = 65536;                  // 65536*8*4 == PIX exactly

    convert2image_gather4<<<blocks, threads>>>(feat, slic4, out);
}

// round 15
// speedup vs baseline: 1.0864x; 1.0043x over previous
#include <cuda_runtime.h>

// ============================================================================
// Convert2ImageLayer: out[b,h,w,:] = feat[b, slic[b,h,w]-1, :]  (0 if invalid)
// Shapes: B=8, N=1024, C=128, H=W=512.
//
// FINAL kernel — HBM-write-roofline.
//   compulsory traffic: 1.074 GB writes (+12 MB reads) -> 134 us floor
//   measured plateau: 141.8-143.7 us over 8 reproductions = ~7.6 TB/s = 95% spec
//
// Configuration (full 14-round sweep, all post-mortemed):
//   - one warp per P=4 pixels, lane l owns float4-chunk l of the 512B row
//   - MLP=4 independent LDG.128 gathers per thread (the entire win, 260->142us;
//     MLP 1/2/8 and 256-bit v8 ops all measured worse)
//   - 65536 x 256-thr CTAs (coarser granularity variants 1-4us worse)
//   - __stcs write-back streaming stores (beats __stwt by 11us: write-back
//     coalesces full 128B lines; evict-first keeps 4MB feat table L2-resident)
//   - single LDG.128 int4 index load on lane 0 + shfl (regs 30, ALU 17.8%)
//   - no bounds guard: 65536 blocks * 8 warps * 4 pixels == PIX exactly
// ============================================================================

static constexpr int  Nc = 1024;
static constexpr int  C4 = 32;            // 128 floats = 32 float4 per pixel
static constexpr int  HW_SHIFT = 18;      // H*W = 2^18 pixels per batch image
static constexpr int  P = 4;              // pixels per warp (measured optimum)

__global__ void __launch_bounds__(256)
convert2image_gather4(const float4* __restrict__ feat,   // [B, N, C/4]
                      const int4*   __restrict__ slic4,  // [B*H*W/4] packed labels
                      float4*       __restrict__ out)    // [B*H*W, C/4]
{
    const long long warp_gid = (long long)blockIdx.x * (blockDim.x >> 5)
                             + (threadIdx.x >> 5);
    const long long pix0 = warp_gid * P;      // grid covers PIX exactly; no guard
    const int lane = threadIdx.x & 31;

    // All P pixels of a warp lie in the same batch image (P divides H*W).
    const int b = (int)(pix0 >> HW_SHIFT);
    const float4* __restrict__ fb = feat + ((long long)b * Nc) * C4;

    // Lane 0 loads all four labels with one LDG.128 (16B sector); shfl parts.
    int4 li = make_int4(0, 0, 0, 0);
    if (lane == 0) li = __ldg(slic4 + warp_gid);

    const int i0 = __shfl_sync(0xffffffffu, li.x, 0) - 1;   // labels 1-indexed
    const int i1 = __shfl_sync(0xffffffffu, li.y, 0) - 1;
    const int i2 = __shfl_sync(0xffffffffu, li.z, 0) - 1;
    const int i3 = __shfl_sync(0xffffffffu, li.w, 0) - 1;
    const int idx[P] = { i0, i1, i2, i3 };

    float4 v[P];
    #pragma unroll
    for (int p = 0; p < P; p++) {
        v[p] = make_float4(0.f, 0.f, 0.f, 0.f);
        if ((unsigned)idx[p] < (unsigned)Nc) {
            v[p] = __ldg(fb + (long long)idx[p] * C4 + lane);  // independent -> MLP=P
        }
    }

    float4* __restrict__ o = out + (pix0 << 5) + lane;
    #pragma unroll
    for (int p = 0; p < P; p++) {
        __stcs(o + (p << 5), v[p]);    // streaming: write-once, evict-first
    }
}

extern "C" void kernel_launch(void* const* d_in, const int* in_sizes, int n_in,
                              void* d_out, int out_size)
{
    const float4* feat  = (const float4*)d_in[0];  // graph_lstm_output fp32 [B,N,C]
    const int4*   slic4 = (const int4*)d_in[1];    // slic_output int32 [B,H,W,1], 16B-aligned
    float4*       out   = (float4*)d_out;          // fp32 [B,H,W,C]

    const int threads = 256;                        // 8 warps -> 32 pixels/block
    const unsigned blocks = 65536;                  // 65536*8*4 == PIX exactly

    convert2image_gather4<<<blocks, threads>>>(feat, slic4, out);
}